// round 8
// baseline (speedup 1.0000x reference)
#include <cuda_runtime.h>
#include <cuda_bf16.h>

#define N_TOTAL 8700
#define N_YOLO  8400
#define N_WORDS 136          // ceil(8700/64)
#define N_PAD   8704
#define LAST_BITS 60         // 8700 - 135*64
#define CAP     8192         // per-column sparse entry capacity
#define MPT     4            // scan: register-resident entries per thread
#define GBLK    272          // persistent grid: 272 blocks, all co-resident (<=2/SM)
#define TPB     256
#define N_TILES (136 * 17)   // mask tiles: 136 i-groups x 17 word-groups

// ---------------- scratch (static device globals; no allocation) ----------------
__device__ float u_x1[N_PAD], u_y1[N_PAD], u_x2[N_PAD], u_y2[N_PAD], u_conf[N_PAD];
__device__ unsigned long long u_key[N_PAD];        // pads stay 0 (never written)
// s_* pads [8700..8703] end up zero: pad ranks collide at 8700 writing zeros; 8701..8703 untouched (zero-init).
__device__ float s_x1[N_PAD], s_y1[N_PAD], s_x2[N_PAD], s_y2[N_PAD], s_conf[N_PAD];
// sparse suppression structure
__device__ int col_count[N_WORDS];
__device__ ulonglong2 col_ent[N_WORDS][CAP];       // .x = row index i, .y = 64-bit word
__device__ unsigned long long g_diag[N_PAD];
__device__ unsigned long long g_hasdiag[N_WORDS];
// monotonic grid-sync counters (never reset; safe across graph replays)
__device__ unsigned int g_syncc[3];

__device__ __forceinline__ void gsync(int s) {
    __syncthreads();
    if (threadIdx.x == 0) {
        __threadfence();
        unsigned int old = atomicAdd(&g_syncc[s], 1u);
        unsigned int target = old - (old % GBLK) + GBLK;
        volatile unsigned int* p = &g_syncc[s];
        while (*p < target) { __nanosleep(64); }
        __threadfence();
    }
    __syncthreads();
}

__global__ void __launch_bounds__(TPB, 2) k_all(
    const float* __restrict__ yb, const float* __restrict__ yc,
    const float* __restrict__ rb, const float* __restrict__ rc,
    float* __restrict__ out)
{
    __shared__ unsigned long long skey[2176];      // rank j-tile (17.4 KB)
    __shared__ int scnt_sh[8][32];
    __shared__ float4 jb[512];                     // mask j boxes (8 KB)
    __shared__ float  ja[512];                     // mask j areas (2 KB)
    __shared__ unsigned long long kw[N_WORDS];     // scan: keep words
    __shared__ unsigned long long hds[N_WORDS];
    __shared__ unsigned long long remv_out[N_WORDS];
    __shared__ int scol[N_WORDS];
    __shared__ unsigned long long s_part[8];

    const int tid = threadIdx.x;
    const int bid = blockIdx.x;

    // ================= PHASE 1: prep (concat+clip+xyxy+key) + scratch init =========
    for (int i = bid * TPB + tid; i < N_PAD; i += GBLK * TPB) {
        if (i < N_WORDS) { col_count[i] = 0; g_hasdiag[i] = 0ull; }
        if (i < N_TOTAL) {
            float cx, cy, w, h, c;
            if (i < N_YOLO) {
                float4 p = *(const float4*)(yb + 4 * i);
                cx = p.x; cy = p.y; w = p.z; h = p.w;
                c = yc[i];
            } else {
                int k = i - N_YOLO;
                float4 p = *(const float4*)(rb + 4 * k);
                cx = p.x; cy = p.y; w = p.z; h = p.w;
                c = rc[k];
            }
            c = fminf(fmaxf(c, 0.0f), 1.0f);
            float hw = __fmul_rn(w, 0.5f);
            float hh = __fmul_rn(h, 0.5f);
            u_x1[i] = __fsub_rn(cx, hw);
            u_y1[i] = __fsub_rn(cy, hh);
            u_x2[i] = __fadd_rn(cx, hw);
            u_y2[i] = __fadd_rn(cy, hh);
            u_conf[i] = c;
            // descending conf, ties -> ascending original index (stable argsort)
            u_key[i] = ((unsigned long long)__float_as_uint(c) << 32)
                     | (unsigned long long)(0xFFFFFFFFu - (unsigned)i);
        }
    }
    gsync(0);

    // ================= PHASE 2: fused rank + scatter ===============================
    // Block owns i-range [bid*32, bid*32+32). 8 j-stripes x 32 i-lanes.
    {
        int il = tid & 31;
        int stripe = tid >> 5;
        int i = bid * 32 + il;                     // covers all of [0, 8704)
        unsigned long long ki = u_key[i];          // pad keys are 0
        int cnt = 0;
        for (int base = 0; base < N_PAD; base += 2176) {
            for (int t = tid; t < 2176; t += TPB) skey[t] = u_key[base + t];
            __syncthreads();
            int lo = stripe * 272;
#pragma unroll 16
            for (int t = 0; t < 272; t++)
                cnt += (skey[lo + t] > ki) ? 1 : 0;
            __syncthreads();
        }
        scnt_sh[stripe][il] = cnt;
        __syncthreads();
        if (tid < 32) {
            int r = 0;
#pragma unroll
            for (int s2 = 0; s2 < 8; s2++) r += scnt_sh[s2][tid];
            int ii = bid * 32 + tid;
            s_x1[r] = u_x1[ii]; s_y1[r] = u_y1[ii];
            s_x2[r] = u_x2[ii]; s_y2[r] = u_y2[ii];
            s_conf[r] = u_conf[ii];
        }
    }
    gsync(1);

    // ================= PHASE 3: sparse suppression build ===========================
    for (int t5 = bid; t5 < N_TILES; t5 += GBLK) {
        int xg = t5 % 136;                 // i-group: i0 = xg*64
        int yw = t5 / 136;                 // word-group: words [yw*8, yw*8+8)
        int i0 = xg * 64;
        int jb0 = yw * 512;
        if (jb0 + 512 <= i0) continue;     // all j < i: block-uniform skip
        __syncthreads();                   // protect jb/ja from previous tile
        for (int t = tid; t < 512; t += TPB) {
            int j = jb0 + t;               // j <= 8703 < N_PAD
            float4 J = make_float4(s_x1[j], s_y1[j], s_x2[j], s_y2[j]);
            jb[t] = J;
            ja[t] = __fmul_rn(__fsub_rn(J.z, J.x), __fsub_rn(J.w, J.y));
        }
        __syncthreads();
        int il = tid & 31;
        int wl = tid >> 5;
        int word = yw * 8 + wl;
        if (word >= xg) {
            int i1 = i0 + il;              // <= 8671 < N_TOTAL
            int i2 = i1 + 32;              // may be pad (zero box -> bits stay 0)
            float ax1 = s_x1[i1], ay1 = s_y1[i1], ax2 = s_x2[i1], ay2 = s_y2[i1];
            float bx1 = s_x1[i2], by1 = s_y1[i2], bx2 = s_x2[i2], by2 = s_y2[i2];
            float aa = __fmul_rn(__fsub_rn(ax2, ax1), __fsub_rn(ay2, ay1));
            float ab = __fmul_rn(__fsub_rn(bx2, bx1), __fsub_rn(by2, by1));
            unsigned long long bits1 = 0ull, bits2 = 0ull;
            int tb = wl * 64;
#pragma unroll 8
            for (int b = 0; b < 64; b++) {
                float4 J = jb[tb + b];
                float aj = ja[tb + b];
                float iw1 = fmaxf(__fsub_rn(fminf(ax2, J.z), fmaxf(ax1, J.x)), 0.0f);
                float ih1 = fmaxf(__fsub_rn(fminf(ay2, J.w), fmaxf(ay1, J.y)), 0.0f);
                float in1 = __fmul_rn(iw1, ih1);
                float un1 = __fsub_rn(__fadd_rn(aa, aj), in1);
                if (in1 > __fmul_rn(0.49f, un1)) {   // safe pre-filter
                    if (__fdiv_rn(in1, fmaxf(un1, 1e-9f)) > 0.5f) bits1 |= (1ull << b);
                }
                float iw2 = fmaxf(__fsub_rn(fminf(bx2, J.z), fmaxf(bx1, J.x)), 0.0f);
                float ih2 = fmaxf(__fsub_rn(fminf(by2, J.w), fmaxf(by1, J.y)), 0.0f);
                float in2 = __fmul_rn(iw2, ih2);
                float un2 = __fsub_rn(__fadd_rn(ab, aj), in2);
                if (in2 > __fmul_rn(0.49f, un2)) {
                    if (__fdiv_rn(in2, fmaxf(un2, 1e-9f)) > 0.5f) bits2 |= (1ull << b);
                }
            }
            if (word == xg) {              // straddling word -> diag entries
                int d1 = il;
                int d2 = il + 32;
                bits1 &= (~0ull << (d1 + 1));
                bits2 = (d2 >= 63) ? 0ull : (bits2 & (~0ull << (d2 + 1)));
                g_diag[i1] = bits1;
                g_diag[i2] = bits2;
                unsigned long long hd = (bits1 ? (1ull << d1) : 0ull)
                                      | (bits2 ? (1ull << d2) : 0ull);
                if (hd) atomicOr(&g_hasdiag[xg], hd);
            } else {                        // word > xg: sparse off-diagonal entries
                if (bits1) {
                    int pos = atomicAdd(&col_count[word], 1);
                    if (pos < CAP)
                        col_ent[word][pos] = make_ulonglong2((unsigned long long)i1, bits1);
                }
                if (bits2) {
                    int pos = atomicAdd(&col_count[word], 1);
                    if (pos < CAP)
                        col_ent[word][pos] = make_ulonglong2((unsigned long long)i2, bits2);
                }
            }
        }
    }
    gsync(2);

    // ================= PHASE 4: scan + output (block 0 only) =======================
    if (bid != 0) return;

    const int wid = tid >> 5, lane = tid & 31;
    if (tid < N_WORDS) {
        hds[tid] = g_hasdiag[tid];
        int c = col_count[tid];
        scol[tid] = (c > CAP) ? CAP : c;
    }
    __syncthreads();

    // register-resident entry sets for groups g (parity) and g+1
    ulonglong2 eA[MPT], eB[MPT];
    {
        int cA = scol[0];
#pragma unroll
        for (int m = 0; m < MPT; m++) {
            int k = tid + (m << 8);
            eA[m] = (k < cA) ? col_ent[0][k] : make_ulonglong2(0ull, 0ull);
        }
        int cB = scol[1];
#pragma unroll
        for (int m = 0; m < MPT; m++) {
            int k = tid + (m << 8);
            eB[m] = (k < cB) ? col_ent[1][k] : make_ulonglong2(0ull, 0ull);
        }
    }

    for (int g = 0; g < N_WORDS; g++) {
        unsigned long long valid = (g == N_WORDS - 1) ? ((1ull << LAST_BITS) - 1ull)
                                                      : ~0ull;
        // t0: speculatively preload up to 4 in-group diag words
        unsigned long long pre_d0 = 0, pre_d1 = 0, pre_d2 = 0, pre_d3 = 0;
        int pre_b0 = -1, pre_b1 = -1, pre_b2 = -1, pre_b3 = -1;
        unsigned long long hd = 0ull;
        if (tid == 0) {
            hd = hds[g] & valid;
            unsigned long long t = hd;
            if (t) { pre_b0 = __ffsll(t) - 1; t &= t - 1; pre_d0 = g_diag[g * 64 + pre_b0]; }
            if (t) { pre_b1 = __ffsll(t) - 1; t &= t - 1; pre_d1 = g_diag[g * 64 + pre_b1]; }
            if (t) { pre_b2 = __ffsll(t) - 1; t &= t - 1; pre_d2 = g_diag[g * 64 + pre_b2]; }
            if (t) { pre_b3 = __ffsll(t) - 1;             pre_d3 = g_diag[g * 64 + pre_b3]; }
        }
        // phase 1: OR keep-gated entries (register-resident; zero-sentinels no-op)
        int cnt = scol[g];
        unsigned long long part = 0ull;
        if (g & 1) {
#pragma unroll
            for (int m = 0; m < MPT; m++) {
                int i = (int)eB[m].x;
                if ((kw[i >> 6] >> (i & 63)) & 1ull) part |= eB[m].y;
            }
        } else {
#pragma unroll
            for (int m = 0; m < MPT; m++) {
                int i = (int)eA[m].x;
                if ((kw[i >> 6] >> (i & 63)) & 1ull) part |= eA[m].y;
            }
        }
        for (int k = (MPT << 8) + tid; k < cnt; k += TPB) {  // overflow fallback (rare)
            ulonglong2 e = col_ent[g][k];
            int i = (int)e.x;
            if ((kw[i >> 6] >> (i & 63)) & 1ull) part |= e.y;
        }
        unsigned lo = __reduce_or_sync(0xFFFFFFFFu, (unsigned)part);
        unsigned hi = __reduce_or_sync(0xFFFFFFFFu, (unsigned)(part >> 32));
        if (lane == 0) s_part[wid] = ((unsigned long long)hi << 32) | lo;
        // prefetch group g+2 into the set just consumed
        int g2 = g + 2;
        if (g2 < N_WORDS) {
            int c2 = scol[g2];
            if (g & 1) {
#pragma unroll
                for (int m = 0; m < MPT; m++) {
                    int k = tid + (m << 8);
                    eB[m] = (k < c2) ? col_ent[g2][k] : make_ulonglong2(0ull, 0ull);
                }
            } else {
#pragma unroll
                for (int m = 0; m < MPT; m++) {
                    int k = tid + (m << 8);
                    eA[m] = (k < c2) ? col_ent[g2][k] : make_ulonglong2(0ull, 0ull);
                }
            }
        }
        __syncthreads();
        // phase 2: t0 combines warp partials + resolves rare in-group chain
        if (tid == 0) {
            unsigned long long removed = 0ull;
#pragma unroll
            for (int w = 0; w < 8; w++) removed |= s_part[w];
            unsigned long long m = hd & ~removed;
            while (m) {
                int b = __ffsll(m) - 1;
                if (!((removed >> b) & 1ull)) {
                    unsigned long long d;
                    if      (b == pre_b0) d = pre_d0;
                    else if (b == pre_b1) d = pre_d1;
                    else if (b == pre_b2) d = pre_d2;
                    else if (b == pre_b3) d = pre_d3;
                    else                  d = g_diag[g * 64 + b];
                    removed |= d;
                }
                m &= m - 1;
                m &= ~removed;
            }
            kw[g] = valid & ~removed;
            remv_out[g] = removed;
        }
        __syncthreads();
    }

    // ---- output: (x1,y1,x2,y2,conf) * keep ----
    for (int r = tid; r < N_TOTAL; r += TPB) {
        bool keep = !((remv_out[r >> 6] >> (r & 63)) & 1ull);
        float m = keep ? 1.0f : 0.0f;
        out[r * 5 + 0] = __fmul_rn(s_x1[r], m);
        out[r * 5 + 1] = __fmul_rn(s_y1[r], m);
        out[r * 5 + 2] = __fmul_rn(s_x2[r], m);
        out[r * 5 + 3] = __fmul_rn(s_y2[r], m);
        out[r * 5 + 4] = __fmul_rn(s_conf[r], m);
    }
}

// ---------------- launch ----------------
extern "C" void kernel_launch(void* const* d_in, const int* in_sizes, int n_in,
                              void* d_out, int out_size) {
    const float* yb = (const float*)d_in[0];   // yolo_cxcywh   [8400,4]
    const float* yc = (const float*)d_in[1];   // yolo_conf     [8400]
    const float* rb = (const float*)d_in[2];   // rtdetr_cxcywh [300,4]
    const float* rc = (const float*)d_in[3];   // rtdetr_conf   [300]
    float* out = (float*)d_out;

    k_all<<<GBLK, TPB>>>(yb, yc, rb, rc, out);
}

// round 9
// speedup vs baseline: 1.1962x; 1.1962x over previous
#include <cuda_runtime.h>
#include <cuda_bf16.h>

#define N_TOTAL 8700
#define N_YOLO  8400
#define N_WORDS 136          // ceil(8700/64)
#define N_PAD   8704
#define LAST_BITS 60         // 8700 - 135*64
#define CAP     8192         // per-column sparse entry capacity (safety bound)
#define MPT     6            // scan: register entries per lane (32*6 = 192/column)

// ---------------- scratch (static device globals; no allocation) ----------------
// s_* pads: [8700] rewritten with zeros each call (pad rank collision); [8701..8703] stay zero-init.
__device__ float s_x1[N_PAD], s_y1[N_PAD], s_x2[N_PAD], s_y2[N_PAD], s_conf[N_PAD];
// sparse suppression structure
__device__ int col_count[N_WORDS];
__device__ ulonglong2 col_ent[N_WORDS][CAP];       // .x = row index i, .y = 64-bit word
__device__ unsigned long long g_diag[N_PAD];
__device__ unsigned long long g_hasdiag[N_WORDS];

// key: descending clipped conf, ties -> ascending original concat index (stable argsort)
__device__ __forceinline__ unsigned long long make_key(
    int j, const float* __restrict__ yc, const float* __restrict__ rc) {
    if (j >= N_TOTAL) return 0ull;                 // pad: never beats a real key
    float c = (j < N_YOLO) ? yc[j] : rc[j - N_YOLO];
    c = fminf(fmaxf(c, 0.0f), 1.0f);
    return ((unsigned long long)__float_as_uint(c) << 32)
         | (unsigned long long)(0xFFFFFFFFu - (unsigned)j);
}

// ---------------- K1: fused rank + scatter (+ scratch init) ----------------
// Block b owns rows [b*32, b*32+32). 8 j-stripes x 32 i-lanes count keys > own key.
__global__ void k_ranksc(const float* __restrict__ yb, const float* __restrict__ yc,
                         const float* __restrict__ rb, const float* __restrict__ rc) {
    __shared__ unsigned long long skey[2176];
    __shared__ int scnt_sh[8][32];
    const int tid = threadIdx.x;
    const int bid = blockIdx.x;
    if (bid == 0 && tid < N_WORDS) { col_count[tid] = 0; g_hasdiag[tid] = 0ull; }
    const int il = tid & 31;
    const int stripe = tid >> 5;
    const int i = bid * 32 + il;                   // covers [0, 8704)
    const unsigned long long ki = make_key(i, yc, rc);
    int cnt = 0;
    for (int base = 0; base < N_PAD; base += 2176) {
        for (int t = tid; t < 2176; t += 256)
            skey[t] = make_key(base + t, yc, rc);
        __syncthreads();
        const int lo = stripe * 272;
#pragma unroll 16
        for (int t = 0; t < 272; t++)
            cnt += (skey[lo + t] > ki) ? 1 : 0;
        __syncthreads();
    }
    scnt_sh[stripe][il] = cnt;
    __syncthreads();
    if (tid < 32) {
        int r = 0;
#pragma unroll
        for (int s2 = 0; s2 < 8; s2++) r += scnt_sh[s2][tid];
        const int ii = bid * 32 + tid;
        float ox1 = 0.f, oy1 = 0.f, ox2 = 0.f, oy2 = 0.f, oc = 0.f;
        if (ii < N_TOTAL) {
            float4 p;
            float c;
            if (ii < N_YOLO) { p = *(const float4*)(yb + 4 * ii); c = yc[ii]; }
            else             { p = *(const float4*)(rb + 4 * (ii - N_YOLO)); c = rc[ii - N_YOLO]; }
            c = fminf(fmaxf(c, 0.0f), 1.0f);
            float hw = __fmul_rn(p.z, 0.5f);
            float hh = __fmul_rn(p.w, 0.5f);
            ox1 = __fsub_rn(p.x, hw);
            oy1 = __fsub_rn(p.y, hh);
            ox2 = __fadd_rn(p.x, hw);
            oy2 = __fadd_rn(p.y, hh);
            oc = c;
        }
        s_x1[r] = ox1; s_y1[r] = oy1;
        s_x2[r] = ox2; s_y2[r] = oy2;
        s_conf[r] = oc;
    }
}

// ---------------- K2: sparse suppression build (i suppresses j>i with iou>0.5) ----------------
#define IT 64   // i rows per block (32 lanes x 2)
#define WT 8    // words per block (8*64 = 512 j's)
__global__ void k_mask() {
    __shared__ float4 jb[WT * 64];
    __shared__ float  ja[WT * 64];
    int i0 = blockIdx.x * IT;                 // 64-aligned => igroup = blockIdx.x
    int w0 = blockIdx.y * WT;
    int jb0 = w0 * 64;
    if (jb0 + WT * 64 <= i0) return;          // block fully below diagonal
    for (int t = threadIdx.x; t < WT * 64; t += blockDim.x) {
        int j = jb0 + t;                      // j <= 8703 < N_PAD
        float4 J = make_float4(s_x1[j], s_y1[j], s_x2[j], s_y2[j]);
        jb[t] = J;
        ja[t] = __fmul_rn(__fsub_rn(J.z, J.x), __fsub_rn(J.w, J.y));
    }
    __syncthreads();
    int il = threadIdx.x & 31;
    int wl = threadIdx.x >> 5;
    int igroup = blockIdx.x;
    int word = w0 + wl;
    if (word < igroup) return;
    int i1 = i0 + il;                         // <= 8671 < N_TOTAL
    int i2 = i1 + 32;                         // may be pad (zero box -> bits stay 0)
    float ax1 = s_x1[i1], ay1 = s_y1[i1], ax2 = s_x2[i1], ay2 = s_y2[i1];
    float bx1 = s_x1[i2], by1 = s_y1[i2], bx2 = s_x2[i2], by2 = s_y2[i2];
    float aa = __fmul_rn(__fsub_rn(ax2, ax1), __fsub_rn(ay2, ay1));
    float ab = __fmul_rn(__fsub_rn(bx2, bx1), __fsub_rn(by2, by1));
    unsigned long long bits1 = 0ull, bits2 = 0ull;
    int tb = wl * 64;
#pragma unroll 8
    for (int b = 0; b < 64; b++) {
        float4 J = jb[tb + b];
        float aj = ja[tb + b];
        float iw1 = fmaxf(__fsub_rn(fminf(ax2, J.z), fmaxf(ax1, J.x)), 0.0f);
        float ih1 = fmaxf(__fsub_rn(fminf(ay2, J.w), fmaxf(ay1, J.y)), 0.0f);
        float in1 = __fmul_rn(iw1, ih1);
        float un1 = __fsub_rn(__fadd_rn(aa, aj), in1);
        if (in1 > __fmul_rn(0.49f, un1)) {    // safe pre-filter (iou<0.5 guaranteed if false)
            if (__fdiv_rn(in1, fmaxf(un1, 1e-9f)) > 0.5f) bits1 |= (1ull << b);
        }
        float iw2 = fmaxf(__fsub_rn(fminf(bx2, J.z), fmaxf(bx1, J.x)), 0.0f);
        float ih2 = fmaxf(__fsub_rn(fminf(by2, J.w), fmaxf(by1, J.y)), 0.0f);
        float in2 = __fmul_rn(iw2, ih2);
        float un2 = __fsub_rn(__fadd_rn(ab, aj), in2);
        if (in2 > __fmul_rn(0.49f, un2)) {
            if (__fdiv_rn(in2, fmaxf(un2, 1e-9f)) > 0.5f) bits2 |= (1ull << b);
        }
    }
    if (word == igroup) {                     // straddling word -> diag entries
        int d1 = il;
        int d2 = il + 32;
        bits1 &= (~0ull << (d1 + 1));
        bits2 = (d2 >= 63) ? 0ull : (bits2 & (~0ull << (d2 + 1)));
        g_diag[i1] = bits1;
        g_diag[i2] = bits2;
        unsigned long long hd = (bits1 ? (1ull << d1) : 0ull)
                              | (bits2 ? (1ull << d2) : 0ull);
        if (hd) atomicOr(&g_hasdiag[igroup], hd);
    } else {                                  // word > igroup: sparse off-diagonal entries
        if (bits1) {
            int pos = atomicAdd(&col_count[word], 1);
            if (pos < CAP) col_ent[word][pos] = make_ulonglong2((unsigned long long)i1, bits1);
        }
        if (bits2) {
            int pos = atomicAdd(&col_count[word], 1);
            if (pos < CAP) col_ent[word][pos] = make_ulonglong2((unsigned long long)i2, bits2);
        }
    }
}

// ---------------- K3: single-warp warp-synchronous scan + output ----------------
__global__ void k_scanout(float* __restrict__ out) {
    __shared__ unsigned long long kw[N_WORDS];     // keep words
    __shared__ unsigned long long remv[N_WORDS];
    __shared__ unsigned long long hds[N_WORDS];
    __shared__ int scol[N_WORDS];
    const int tid = threadIdx.x;
    if (tid < N_WORDS) {
        hds[tid] = g_hasdiag[tid];
        int c = col_count[tid];
        scol[tid] = (c > CAP) ? CAP : c;
    }
    __syncthreads();

    if (tid < 32) {                                // warp 0 does the whole scan
        const int lane = tid;
        // register-resident entry sets for groups g (parity) and g+1
        ulonglong2 eA[MPT], eB[MPT];
        {
            int cA = scol[0];
#pragma unroll
            for (int m = 0; m < MPT; m++) {
                int k = lane + (m << 5);
                eA[m] = (k < cA) ? col_ent[0][k] : make_ulonglong2(0ull, 0ull);
            }
            int cB = scol[1];
#pragma unroll
            for (int m = 0; m < MPT; m++) {
                int k = lane + (m << 5);
                eB[m] = (k < cB) ? col_ent[1][k] : make_ulonglong2(0ull, 0ull);
            }
        }
        for (int g = 0; g < N_WORDS; g++) {
            unsigned long long valid = (g == N_WORDS - 1) ? ((1ull << LAST_BITS) - 1ull)
                                                          : ~0ull;
            // lane 0: speculatively preload up to 4 in-group diag words
            unsigned long long pre_d0 = 0, pre_d1 = 0, pre_d2 = 0, pre_d3 = 0;
            int pre_b0 = -1, pre_b1 = -1, pre_b2 = -1, pre_b3 = -1;
            unsigned long long hd = 0ull;
            if (lane == 0) {
                hd = hds[g] & valid;
                unsigned long long t = hd;
                if (t) { pre_b0 = __ffsll(t) - 1; t &= t - 1; pre_d0 = g_diag[g * 64 + pre_b0]; }
                if (t) { pre_b1 = __ffsll(t) - 1; t &= t - 1; pre_d1 = g_diag[g * 64 + pre_b1]; }
                if (t) { pre_b2 = __ffsll(t) - 1; t &= t - 1; pre_d2 = g_diag[g * 64 + pre_b2]; }
                if (t) { pre_b3 = __ffsll(t) - 1;             pre_d3 = g_diag[g * 64 + pre_b3]; }
            }
            // phase 1: OR keep-gated entries (register-resident; zero-sentinels no-op)
            int cnt = scol[g];
            unsigned long long part = 0ull;
            if (g & 1) {
#pragma unroll
                for (int m = 0; m < MPT; m++) {
                    int i = (int)eB[m].x;
                    if ((kw[i >> 6] >> (i & 63)) & 1ull) part |= eB[m].y;
                }
            } else {
#pragma unroll
                for (int m = 0; m < MPT; m++) {
                    int i = (int)eA[m].x;
                    if ((kw[i >> 6] >> (i & 63)) & 1ull) part |= eA[m].y;
                }
            }
            for (int k = (MPT << 5) + lane; k < cnt; k += 32) {   // overflow fallback
                ulonglong2 e = col_ent[g][k];
                int i = (int)e.x;
                if ((kw[i >> 6] >> (i & 63)) & 1ull) part |= e.y;
            }
            unsigned lo = __reduce_or_sync(0xFFFFFFFFu, (unsigned)part);
            unsigned hi = __reduce_or_sync(0xFFFFFFFFu, (unsigned)(part >> 32));
            // prefetch group g+2 into the buffer just consumed
            int g2 = g + 2;
            if (g2 < N_WORDS) {
                int c2 = scol[g2];
                if (g & 1) {
#pragma unroll
                    for (int m = 0; m < MPT; m++) {
                        int k = lane + (m << 5);
                        eB[m] = (k < c2) ? col_ent[g2][k] : make_ulonglong2(0ull, 0ull);
                    }
                } else {
#pragma unroll
                    for (int m = 0; m < MPT; m++) {
                        int k = lane + (m << 5);
                        eA[m] = (k < c2) ? col_ent[g2][k] : make_ulonglong2(0ull, 0ull);
                    }
                }
            }
            // phase 2: lane 0 resolves rare in-group chain, commits keep word
            if (lane == 0) {
                unsigned long long removed = ((unsigned long long)hi << 32) | lo;
                unsigned long long m = hd & ~removed;
                while (m) {
                    int b = __ffsll(m) - 1;
                    if (!((removed >> b) & 1ull)) {
                        unsigned long long d;
                        if      (b == pre_b0) d = pre_d0;
                        else if (b == pre_b1) d = pre_d1;
                        else if (b == pre_b2) d = pre_d2;
                        else if (b == pre_b3) d = pre_d3;
                        else                  d = g_diag[g * 64 + b];
                        removed |= d;
                    }
                    m &= m - 1;
                    m &= ~removed;
                }
                kw[g] = valid & ~removed;
                remv[g] = removed;
            }
            __syncwarp();
        }
    }
    __syncthreads();

    // output: (x1,y1,x2,y2,conf) * keep
    for (int r = tid; r < N_TOTAL; r += 256) {
        bool keep = !((remv[r >> 6] >> (r & 63)) & 1ull);
        float m = keep ? 1.0f : 0.0f;
        out[r * 5 + 0] = __fmul_rn(s_x1[r], m);
        out[r * 5 + 1] = __fmul_rn(s_y1[r], m);
        out[r * 5 + 2] = __fmul_rn(s_x2[r], m);
        out[r * 5 + 3] = __fmul_rn(s_y2[r], m);
        out[r * 5 + 4] = __fmul_rn(s_conf[r], m);
    }
}

// ---------------- launch ----------------
extern "C" void kernel_launch(void* const* d_in, const int* in_sizes, int n_in,
                              void* d_out, int out_size) {
    const float* yb = (const float*)d_in[0];   // yolo_cxcywh   [8400,4]
    const float* yc = (const float*)d_in[1];   // yolo_conf     [8400]
    const float* rb = (const float*)d_in[2];   // rtdetr_cxcywh [300,4]
    const float* rc = (const float*)d_in[3];   // rtdetr_conf   [300]
    float* out = (float*)d_out;

    k_ranksc<<<N_PAD / 32, 256>>>(yb, yc, rb, rc);       // 272 blocks
    k_mask<<<dim3(N_PAD / IT, 17), 256>>>();             // (136, 17)
    k_scanout<<<1, 256>>>(out);
}

// round 10
// speedup vs baseline: 1.2669x; 1.0591x over previous
#include <cuda_runtime.h>
#include <cuda_bf16.h>

#define N_TOTAL 8700
#define N_YOLO  8400
#define N_WORDS 136          // ceil(8700/64)
#define N_PAD   8704
#define LAST_BITS 60         // 8700 - 135*64
#define CAP     8192         // per-column sparse entry capacity (safety bound)
#define MPT     4            // scan: register entries per thread (256*4 = 1024/column)

// ---------------- scratch (static device globals; no allocation) ----------------
// s_* pads: [8700] rewritten with zeros each call (pad rank collision); [8701..8703] stay zero-init.
__device__ float s_x1[N_PAD], s_y1[N_PAD], s_x2[N_PAD], s_y2[N_PAD], s_conf[N_PAD];
// sparse suppression structure
__device__ int col_count[N_WORDS];
__device__ ulonglong2 col_ent[N_WORDS][CAP];       // .x = row index i, .y = 64-bit word
__device__ unsigned long long g_diag[N_PAD];
__device__ unsigned long long g_hasdiag[N_WORDS];

// key: descending clipped conf, ties -> ascending original concat index (stable argsort)
__device__ __forceinline__ unsigned long long make_key(
    int j, const float* __restrict__ yc, const float* __restrict__ rc) {
    if (j >= N_TOTAL) return 0ull;                 // pad: never beats a real key
    float c = (j < N_YOLO) ? yc[j] : rc[j - N_YOLO];
    c = fminf(fmaxf(c, 0.0f), 1.0f);
    return ((unsigned long long)__float_as_uint(c) << 32)
         | (unsigned long long)(0xFFFFFFFFu - (unsigned)j);
}

// ---------------- K1: fused rank + scatter (+ scratch init), 512 threads ----------------
// Block b owns rows [b*32, b*32+32). 16 j-stripes x 32 i-lanes count keys > own key.
#define RTPB 512
__global__ void __launch_bounds__(RTPB) k_ranksc(
        const float* __restrict__ yb, const float* __restrict__ yc,
        const float* __restrict__ rb, const float* __restrict__ rc) {
    __shared__ unsigned long long skey[2176];
    __shared__ int scnt_sh[16][32];
    const int tid = threadIdx.x;
    const int bid = blockIdx.x;
    if (bid == 0 && tid < N_WORDS) { col_count[tid] = 0; g_hasdiag[tid] = 0ull; }
    const int il = tid & 31;
    const int stripe = tid >> 5;                   // 0..15
    const int i = bid * 32 + il;                   // covers [0, 8704)
    const unsigned long long ki = make_key(i, yc, rc);
    int cnt = 0;
    for (int base = 0; base < N_PAD; base += 2176) {
        for (int t = tid; t < 2176; t += RTPB)
            skey[t] = make_key(base + t, yc, rc);
        __syncthreads();
        const int lo = stripe * 136;
#pragma unroll 8
        for (int t = 0; t < 136; t++)
            cnt += (skey[lo + t] > ki) ? 1 : 0;
        __syncthreads();
    }
    scnt_sh[stripe][il] = cnt;
    __syncthreads();
    if (tid < 32) {
        int r = 0;
#pragma unroll
        for (int s2 = 0; s2 < 16; s2++) r += scnt_sh[s2][tid];
        const int ii = bid * 32 + tid;
        float ox1 = 0.f, oy1 = 0.f, ox2 = 0.f, oy2 = 0.f, oc = 0.f;
        if (ii < N_TOTAL) {
            float4 p;
            float c;
            if (ii < N_YOLO) { p = *(const float4*)(yb + 4 * ii); c = yc[ii]; }
            else             { p = *(const float4*)(rb + 4 * (ii - N_YOLO)); c = rc[ii - N_YOLO]; }
            c = fminf(fmaxf(c, 0.0f), 1.0f);
            float hw = __fmul_rn(p.z, 0.5f);
            float hh = __fmul_rn(p.w, 0.5f);
            ox1 = __fsub_rn(p.x, hw);
            oy1 = __fsub_rn(p.y, hh);
            ox2 = __fadd_rn(p.x, hw);
            oy2 = __fadd_rn(p.y, hh);
            oc = c;
        }
        s_x1[r] = ox1; s_y1[r] = oy1;
        s_x2[r] = ox2; s_y2[r] = oy2;
        s_conf[r] = oc;
    }
}

// ---------------- K2: sparse suppression build (i suppresses j>i with iou>0.5) ----------------
#define IT 64   // i rows per block (32 lanes x 2)
#define WT 8    // words per block (8*64 = 512 j's)
__global__ void k_mask() {
    __shared__ float4 jb[WT * 64];
    __shared__ float  ja[WT * 64];
    int i0 = blockIdx.x * IT;                 // 64-aligned => igroup = blockIdx.x
    int w0 = blockIdx.y * WT;
    int jb0 = w0 * 64;
    if (jb0 + WT * 64 <= i0) return;          // block fully below diagonal
    for (int t = threadIdx.x; t < WT * 64; t += blockDim.x) {
        int j = jb0 + t;                      // j <= 8703 < N_PAD
        float4 J = make_float4(s_x1[j], s_y1[j], s_x2[j], s_y2[j]);
        jb[t] = J;
        ja[t] = __fmul_rn(__fsub_rn(J.z, J.x), __fsub_rn(J.w, J.y));
    }
    __syncthreads();
    int il = threadIdx.x & 31;
    int wl = threadIdx.x >> 5;
    int igroup = blockIdx.x;
    int word = w0 + wl;
    if (word < igroup) return;
    int i1 = i0 + il;                         // <= 8671 < N_TOTAL
    int i2 = i1 + 32;                         // may be pad (zero box -> bits stay 0)
    float ax1 = s_x1[i1], ay1 = s_y1[i1], ax2 = s_x2[i1], ay2 = s_y2[i1];
    float bx1 = s_x1[i2], by1 = s_y1[i2], bx2 = s_x2[i2], by2 = s_y2[i2];
    float aa = __fmul_rn(__fsub_rn(ax2, ax1), __fsub_rn(ay2, ay1));
    float ab = __fmul_rn(__fsub_rn(bx2, bx1), __fsub_rn(by2, by1));
    unsigned long long bits1 = 0ull, bits2 = 0ull;
    int tb = wl * 64;
#pragma unroll 8
    for (int b = 0; b < 64; b++) {
        float4 J = jb[tb + b];
        float aj = ja[tb + b];
        float iw1 = fmaxf(__fsub_rn(fminf(ax2, J.z), fmaxf(ax1, J.x)), 0.0f);
        float ih1 = fmaxf(__fsub_rn(fminf(ay2, J.w), fmaxf(ay1, J.y)), 0.0f);
        float in1 = __fmul_rn(iw1, ih1);
        float un1 = __fsub_rn(__fadd_rn(aa, aj), in1);
        if (in1 > __fmul_rn(0.49f, un1)) {    // safe pre-filter (iou<0.5 guaranteed if false)
            if (__fdiv_rn(in1, fmaxf(un1, 1e-9f)) > 0.5f) bits1 |= (1ull << b);
        }
        float iw2 = fmaxf(__fsub_rn(fminf(bx2, J.z), fmaxf(bx1, J.x)), 0.0f);
        float ih2 = fmaxf(__fsub_rn(fminf(by2, J.w), fmaxf(by1, J.y)), 0.0f);
        float in2 = __fmul_rn(iw2, ih2);
        float un2 = __fsub_rn(__fadd_rn(ab, aj), in2);
        if (in2 > __fmul_rn(0.49f, un2)) {
            if (__fdiv_rn(in2, fmaxf(un2, 1e-9f)) > 0.5f) bits2 |= (1ull << b);
        }
    }
    if (word == igroup) {                     // straddling word -> diag entries
        int d1 = il;
        int d2 = il + 32;
        bits1 &= (~0ull << (d1 + 1));
        bits2 = (d2 >= 63) ? 0ull : (bits2 & (~0ull << (d2 + 1)));
        g_diag[i1] = bits1;
        g_diag[i2] = bits2;
        unsigned long long hd = (bits1 ? (1ull << d1) : 0ull)
                              | (bits2 ? (1ull << d2) : 0ull);
        if (hd) atomicOr(&g_hasdiag[igroup], hd);
    } else {                                  // word > igroup: sparse off-diagonal entries
        if (bits1) {
            int pos = atomicAdd(&col_count[word], 1);
            if (pos < CAP) col_ent[word][pos] = make_ulonglong2((unsigned long long)i1, bits1);
        }
        if (bits2) {
            int pos = atomicAdd(&col_count[word], 1);
            if (pos < CAP) col_ent[word][pos] = make_ulonglong2((unsigned long long)i2, bits2);
        }
    }
}

// ---------------- K3: 8-warp scan (capacity 1024, d2 prefetch) + fused output ----------------
__global__ void k_scanout(float* __restrict__ out) {
    __shared__ unsigned long long kw[N_WORDS];     // keep words
    __shared__ unsigned long long hds[N_WORDS];
    __shared__ unsigned long long remv_out[N_WORDS];
    __shared__ int scol[N_WORDS];
    __shared__ unsigned long long s_part[8];
    const int tid = threadIdx.x;
    const int wid = tid >> 5, lane = tid & 31;
    if (tid < N_WORDS) {
        hds[tid] = g_hasdiag[tid];
        int c = col_count[tid];
        scol[tid] = (c > CAP) ? CAP : c;
    }
    __syncthreads();

    // register-resident entry sets for groups g (parity) and g+1
    ulonglong2 eA[MPT], eB[MPT];
    {
        int cA = scol[0];
#pragma unroll
        for (int m = 0; m < MPT; m++) {
            int k = tid + (m << 8);
            eA[m] = (k < cA) ? col_ent[0][k] : make_ulonglong2(0ull, 0ull);
        }
        int cB = scol[1];
#pragma unroll
        for (int m = 0; m < MPT; m++) {
            int k = tid + (m << 8);
            eB[m] = (k < cB) ? col_ent[1][k] : make_ulonglong2(0ull, 0ull);
        }
    }

    for (int g = 0; g < N_WORDS; g++) {
        unsigned long long valid = (g == N_WORDS - 1) ? ((1ull << LAST_BITS) - 1ull)
                                                      : ~0ull;
        // t0: speculatively preload up to 4 in-group diag words
        unsigned long long pre_d0 = 0, pre_d1 = 0, pre_d2 = 0, pre_d3 = 0;
        int pre_b0 = -1, pre_b1 = -1, pre_b2 = -1, pre_b3 = -1;
        unsigned long long hd = 0ull;
        if (tid == 0) {
            hd = hds[g] & valid;
            unsigned long long t = hd;
            if (t) { pre_b0 = __ffsll(t) - 1; t &= t - 1; pre_d0 = g_diag[g * 64 + pre_b0]; }
            if (t) { pre_b1 = __ffsll(t) - 1; t &= t - 1; pre_d1 = g_diag[g * 64 + pre_b1]; }
            if (t) { pre_b2 = __ffsll(t) - 1; t &= t - 1; pre_d2 = g_diag[g * 64 + pre_b2]; }
            if (t) { pre_b3 = __ffsll(t) - 1;             pre_d3 = g_diag[g * 64 + pre_b3]; }
        }
        // phase 1: OR keep-gated entries (register-resident; zero-sentinels no-op)
        int cnt = scol[g];
        unsigned long long part = 0ull;
        if (g & 1) {
#pragma unroll
            for (int m = 0; m < MPT; m++) {
                int i = (int)eB[m].x;
                if ((kw[i >> 6] >> (i & 63)) & 1ull) part |= eB[m].y;
            }
        } else {
#pragma unroll
            for (int m = 0; m < MPT; m++) {
                int i = (int)eA[m].x;
                if ((kw[i >> 6] >> (i & 63)) & 1ull) part |= eA[m].y;
            }
        }
        for (int k = (MPT << 8) + tid; k < cnt; k += 256) {   // overflow fallback (rare)
            ulonglong2 e = col_ent[g][k];
            int i = (int)e.x;
            if ((kw[i >> 6] >> (i & 63)) & 1ull) part |= e.y;
        }
        unsigned lo = __reduce_or_sync(0xFFFFFFFFu, (unsigned)part);
        unsigned hi = __reduce_or_sync(0xFFFFFFFFu, (unsigned)(part >> 32));
        if (lane == 0) s_part[wid] = ((unsigned long long)hi << 32) | lo;
        // prefetch group g+2 into the buffer just consumed
        int g2 = g + 2;
        if (g2 < N_WORDS) {
            int c2 = scol[g2];
            if (g & 1) {
#pragma unroll
                for (int m = 0; m < MPT; m++) {
                    int k = tid + (m << 8);
                    eB[m] = (k < c2) ? col_ent[g2][k] : make_ulonglong2(0ull, 0ull);
                }
            } else {
#pragma unroll
                for (int m = 0; m < MPT; m++) {
                    int k = tid + (m << 8);
                    eA[m] = (k < c2) ? col_ent[g2][k] : make_ulonglong2(0ull, 0ull);
                }
            }
        }
        __syncthreads();
        // phase 2: t0 combines warp partials + resolves rare in-group chain
        if (tid == 0) {
            unsigned long long removed = 0ull;
#pragma unroll
            for (int w = 0; w < 8; w++) removed |= s_part[w];
            unsigned long long m = hd & ~removed;
            while (m) {
                int b = __ffsll(m) - 1;
                if (!((removed >> b) & 1ull)) {
                    unsigned long long d;
                    if      (b == pre_b0) d = pre_d0;
                    else if (b == pre_b1) d = pre_d1;
                    else if (b == pre_b2) d = pre_d2;
                    else if (b == pre_b3) d = pre_d3;
                    else                  d = g_diag[g * 64 + b];
                    removed |= d;
                }
                m &= m - 1;
                m &= ~removed;
            }
            kw[g] = valid & ~removed;
            remv_out[g] = removed;
        }
        __syncthreads();
    }

    // fused output: (x1,y1,x2,y2,conf) * keep
    for (int r = tid; r < N_TOTAL; r += 256) {
        bool keep = !((remv_out[r >> 6] >> (r & 63)) & 1ull);
        float m = keep ? 1.0f : 0.0f;
        out[r * 5 + 0] = __fmul_rn(s_x1[r], m);
        out[r * 5 + 1] = __fmul_rn(s_y1[r], m);
        out[r * 5 + 2] = __fmul_rn(s_x2[r], m);
        out[r * 5 + 3] = __fmul_rn(s_y2[r], m);
        out[r * 5 + 4] = __fmul_rn(s_conf[r], m);
    }
}

// ---------------- launch ----------------
extern "C" void kernel_launch(void* const* d_in, const int* in_sizes, int n_in,
                              void* d_out, int out_size) {
    const float* yb = (const float*)d_in[0];   // yolo_cxcywh   [8400,4]
    const float* yc = (const float*)d_in[1];   // yolo_conf     [8400]
    const float* rb = (const float*)d_in[2];   // rtdetr_cxcywh [300,4]
    const float* rc = (const float*)d_in[3];   // rtdetr_conf   [300]
    float* out = (float*)d_out;

    k_ranksc<<<N_PAD / 32, RTPB>>>(yb, yc, rb, rc);      // 272 blocks x 512
    k_mask<<<dim3(N_PAD / IT, 17), 256>>>();             // (136, 17)
    k_scanout<<<1, 256>>>(out);
}